// round 15
// baseline (speedup 1.0000x reference)
#include <cuda_runtime.h>
#include <cuda_fp16.h>
#include <math.h>

#define BATCH 4096
#define SEQL 512
#define GRID_MAIN 888
#define NB_CODE 391            // ceil(3125/8): one code per warp

__device__ __align__(128) float    g_F2[25 * 32];     // e2*h2 (fp32)
__device__ __align__(128) float    g_F3[125 * 32];    // e3*h3 (fp32)
// fused record by c5: [32 x fp16 (e4*h4 of c5%625) | 32 x fp16 (e5*h5)]
// record 3125 = zeros; records 3126+c4 = [F4(c4) | zeros] for the l=508 edge
__device__ __align__(128) unsigned g_F45h[3751 * 32];
__device__ __align__(128) float    g_E4f[625];        // e4 by 4-gram code
__device__ __align__(128) __half   g_E5h[3125];       // e5 by 5-gram code (fp16)
__device__ __align__(128) float    g_E3[125], g_E2[25];
__device__ __align__(128) float    g_Wt[128 * 64];    // proj_w transposed
__device__ unsigned g_row_ctr;

__device__ __forceinline__ float gelu_exact(float x) {
    return 0.5f * x * (1.0f + erff(x * 0.70710678118654752440f));
}
__device__ __forceinline__ unsigned long long f2add(unsigned long long a, unsigned long long b) {
    unsigned long long r; asm("add.rn.f32x2 %0,%1,%2;" : "=l"(r) : "l"(a), "l"(b)); return r;
}
__device__ __forceinline__ unsigned long long f2fma(unsigned long long a, unsigned long long b, unsigned long long c) {
    unsigned long long r; asm("fma.rn.f32x2 %0,%1,%2,%3;" : "=l"(r) : "l"(a), "l"(b), "l"(c)); return r;
}
__device__ __forceinline__ unsigned long long f2pack(float lo, float hi) {
    unsigned long long r; asm("mov.b64 %0,{%1,%2};" : "=l"(r) : "f"(lo), "f"(hi)); return r;
}
__device__ __forceinline__ unsigned long long h2f2(unsigned u) {
    __half2 h = *(__half2*)&u;
    float2 f = __half22float2(h);
    return f2pack(f.x, f.y);
}
union U2F4 { ulonglong2 u; float4 f; };

// ---------------------------------------------------------------------------
// Fused setup kernel — ONE code per warp (4x wider than before).
// Blocks 0..390  : 8 codes each. Blocks 391..394: Wt transpose.
// Block 395      : zero dummy record 3125, reset row counter.
// ---------------------------------------------------------------------------
__global__ __launch_bounds__(256) void setup_kernel(
    const float* __restrict__ emb,
    const float* __restrict__ w0, const float* __restrict__ b0, const float* __restrict__ a0,
    const float* __restrict__ w1, const float* __restrict__ b1, const float* __restrict__ a1,
    const float* __restrict__ w2, const float* __restrict__ b2, const float* __restrict__ a2,
    const float* __restrict__ w3, const float* __restrict__ b3, const float* __restrict__ a3,
    const float* __restrict__ proj_w)
{
    const int b = blockIdx.x, tid = threadIdx.x, lane = tid & 31, warp = tid >> 5;

    if (b >= NB_CODE) {
        if (b < NB_CODE + 4) {
            int j0 = (b - NB_CODE) * 2048 + tid;
            #pragma unroll
            for (int r = 0; r < 8; r++) {
                int j = j0 + r * 256;
                int k = j >> 6, o = j & 63;
                g_Wt[j] = __ldg(&proj_w[o * 128 + k]);
            }
        } else {
            if (tid == 0) g_row_ctr = 0;
            if (tid < 32) g_F45h[3125 * 32 + tid] = 0u;
        }
        return;
    }

    __shared__ float pdall[14 * 160];
    __shared__ float sb[4][32], sa[4][32];
    for (int i = tid; i < 14 * 160; i += 256) {
        int l8 = i & 31;
        int t  = (i >> 5) % 5;
        int slot = i / 160;
        const float* W; int KS, j;
        if (slot < 2)      { W = w0; KS = 2; j = slot; }
        else if (slot < 5) { W = w1; KS = 3; j = slot - 2; }
        else if (slot < 9) { W = w2; KS = 4; j = slot - 5; }
        else               { W = w3; KS = 5; j = slot - 9; }
        float acc = 0.f;
        #pragma unroll
        for (int c = 0; c < 8; c++)
            acc += __ldg(&emb[t * 8 + c]) * __ldg(&W[l8 * 8 * KS + c * KS + j]);
        pdall[slot * 160 + t * 32 + l8] = acc;
    }
    if (tid < 128) {
        int br = tid >> 5, f = tid & 31;
        const float* Bv = (br == 0) ? b0 : (br == 1) ? b1 : (br == 2) ? b2 : b3;
        const float* Av = (br == 0) ? a0 : (br == 1) ? a1 : (br == 2) ? a2 : a3;
        sb[br][f] = __ldg(&Bv[f]);
        sa[br][f] = __ldg(&Av[f]);
    }
    __syncthreads();

    const int c = b * 8 + warp;       // one code per warp
    if (c >= 3125) return;
    {
        int t0 = c % 5, r = c / 5;
        int t1 = r % 5; r /= 5;
        int t2 = r % 5; r /= 5;
        int t3 = r % 5, t4 = r / 5;

        float acc2 = sb[0][lane] + pdall[0*160 + t0*32 + lane] + pdall[1*160 + t1*32 + lane];
        float acc3 = sb[1][lane] + pdall[2*160 + t0*32 + lane] + pdall[3*160 + t1*32 + lane]
                                 + pdall[4*160 + t2*32 + lane];
        float acc4 = sb[2][lane] + pdall[5*160 + t0*32 + lane] + pdall[6*160 + t1*32 + lane]
                                 + pdall[7*160 + t2*32 + lane] + pdall[8*160 + t3*32 + lane];
        float acc5 = sb[3][lane] + pdall[9*160 + t0*32 + lane] + pdall[10*160 + t1*32 + lane]
                                 + pdall[11*160 + t2*32 + lane] + pdall[12*160 + t3*32 + lane]
                                 + pdall[13*160 + t4*32 + lane];
        float h2 = gelu_exact(acc2), h3 = gelu_exact(acc3);
        float h4 = gelu_exact(acc4), h5 = gelu_exact(acc5);

        float s2 = h2 * sa[0][lane], s3 = h3 * sa[1][lane];
        float s4 = h4 * sa[2][lane], s5 = h5 * sa[3][lane];
        #pragma unroll
        for (int o = 16; o; o >>= 1) {
            s2 += __shfl_xor_sync(0xffffffffu, s2, o);
            s3 += __shfl_xor_sync(0xffffffffu, s3, o);
            s4 += __shfl_xor_sync(0xffffffffu, s4, o);
            s5 += __shfl_xor_sync(0xffffffffu, s5, o);
        }
        float e2 = __expf(s2), e3 = __expf(s3), e4 = __expf(s4), e5 = __expf(s5);

        // ---- fused ks4/ks5 record (e4 == E4[c%625] since acc4 uses t0..t3) ----
        {
            float v4 = h4 * e4, v5 = h5 * e5;
            int src = (lane & 15) * 2;
            float lo4 = __shfl_sync(0xffffffffu, v4, src);
            float hi4 = __shfl_sync(0xffffffffu, v4, src + 1);
            float lo5 = __shfl_sync(0xffffffffu, v5, src);
            float hi5 = __shfl_sync(0xffffffffu, v5, src + 1);
            __half2 p4 = __floats2half2_rn(lo4, hi4);
            __half2 p5 = __floats2half2_rn(lo5, hi5);
            unsigned u4 = *(unsigned*)&p4, u5 = *(unsigned*)&p5;
            unsigned u = (lane < 16) ? u4 : u5;
            g_F45h[c * 32 + lane] = u;
            if (c < 625)   // edge record for l=508: F4 valid, F5 zero
                g_F45h[(3126 + c) * 32 + lane] = (lane < 16) ? u4 : 0u;
        }
        if (lane == 0) g_E5h[c] = __float2half_rn(e5);
        if (c < 625 && lane == 1) g_E4f[c] = e4;
        if (c < 125) { g_F3[c * 32 + lane] = h3 * e3; if (lane == 0) g_E3[c] = e3; }
        if (c < 25)  { g_F2[c * 32 + lane] = h2 * e2; if (lane == 0) g_E2[c] = e2; }
    }
}

// ---------------------------------------------------------------------------
// Persistent main kernel: fused pooling + smem E-tables for Z (no gmem gather
// in phase 1 at all).
// ---------------------------------------------------------------------------
__global__ __launch_bounds__(256, 6) void seqcnn_main(
    const int*   __restrict__ x_idx,
    const float* __restrict__ proj_b,
    const float* __restrict__ gamma,
    const float* __restrict__ beta,
    float*       __restrict__ out)
{
    __shared__ unsigned char  xrow[SEQL + 8];
    __shared__ unsigned short code5[SEQL];    // fused record index (0..3750)
    __shared__ int            cnt3[125];
    __shared__ int            c2fix;
    __shared__ float          sE4[625];
    __shared__ __half         sE5h[3125];
    __shared__ float          sE3[125];
    __shared__ float          sE2[25];
    __shared__ float2         zarr45[8];
    __shared__ float2         zarr23[8];
    __shared__ float4         partial[2][64];   // ks2, ks3
    __shared__ float4         partial45[2][64]; // ks4, ks5 (from fused lanes)
    __shared__ float4         feats4[32];       // viewed as float[128]
    __shared__ float          prsum[256];
    __shared__ float          lnred[128];
    __shared__ float          lnstats[2];
    __shared__ unsigned       row_sh;

    const int tid = threadIdx.x, lane = tid & 31, warp = tid >> 5;
    const int grp = lane >> 3, fl = lane & 7;
    const ulonglong2* F2v = (const ulonglong2*)g_F2;
    const ulonglong2* F3v = (const ulonglong2*)g_F3;
    const uint4*      F45 = (const uint4*)g_F45h;   // record = 8 x uint4

    // stage E-tables once per persistent block
    for (int i = tid; i < 3125; i += 256) sE5h[i] = g_E5h[i];
    for (int i = tid; i < 625;  i += 256) sE4[i]  = g_E4f[i];
    if (tid < 125) sE3[tid] = g_E3[tid];
    if (tid >= 128 && tid < 153) sE2[tid - 128] = g_E2[tid - 128];

    for (;;) {
        if (tid == 0) row_sh = atomicAdd(&g_row_ctr, 1u);
        __syncthreads();
        const unsigned row = row_sh;
        if (row >= BATCH) break;

        // ---- phase 0: stage row (vectorized) + zero counts ----
        {
            const int4* src = (const int4*)(x_idx + row * SEQL);
            if (tid < 128) {
                int4 v = __ldg(&src[tid]);
                uchar4 pk = make_uchar4((unsigned char)v.x, (unsigned char)v.y,
                                        (unsigned char)v.z, (unsigned char)v.w);
                *(uchar4*)&xrow[tid * 4] = pk;
            }
        }
        if (tid < 8) xrow[SEQL + tid] = 0;
        if (tid < 125) cnt3[tid] = 0;
        __syncthreads();

        // ---- phase 1: integer hist + Z4/Z5 from smem E-tables ----
        {
            const int la = tid, lb = tid + 256;
            int x0a = xrow[la], x1a = xrow[la+1], x2a = xrow[la+2], x3a = xrow[la+3], x4a = xrow[la+4];
            int x0b = xrow[lb], x1b = xrow[lb+1], x2b = xrow[lb+2], x3b = xrow[lb+3], x4b = xrow[lb+4];
            int c3a = x0a + 5*x1a + 25*x2a, c4a = c3a + 125*x3a, c5a = c4a + 625*x4a;
            int c2b = x0b + 5*x1b;
            int c3b = c2b + 25*x2b, c4b = c3b + 125*x3b, c5b = c4b + 625*x4b;

            atomicAdd(&cnt3[c3a], 1);
            code5[la] = (unsigned short)c5a;
            float z4 = sE4[c4a];
            float z5 = __half2float(sE5h[c5a]);

            if (lb < 510) atomicAdd(&cnt3[c3b], 1);
            int c5s = (lb < 508) ? c5b : (lb == 508 ? 3126 + c4b : 3125);
            code5[lb] = (unsigned short)c5s;
            if (lb < 509) z4 += sE4[c4b];   // e4 valid through l=508
            if (lb < 508) z5 += __half2float(sE5h[c5b]);
            if (lb == 510) c2fix = c2b;

            #pragma unroll
            for (int o = 16; o; o >>= 1) {
                z4 += __shfl_xor_sync(0xffffffffu, z4, o);
                z5 += __shfl_xor_sync(0xffffffffu, z5, o);
            }
            if (lane == 0) zarr45[warp] = make_float2(z4, z5);
        }
        __syncthreads();

        const int p = warp * 4 + grp;   // group id 0..31

        // ---- phase 2a: fused ks4+ks5 pooling: ONE LDG.128 per position ----
        unsigned long long a0 = 0, a1 = 0, a2 = 0, a3 = 0;
        #pragma unroll 4
        for (int it = 0; it < 16; it++) {
            int c5 = code5[p + it * 32];
            uint4 q = __ldg(&F45[c5 * 8 + fl]);
            a0 = f2add(a0, h2f2(q.x));
            a1 = f2add(a1, h2f2(q.y));
            a2 = f2add(a2, h2f2(q.z));
            a3 = f2add(a3, h2f2(q.w));
        }

        // ---- phase 2b: ks3 dense over 125 codes (counts as weights) ----
        unsigned long long a3lo = 0, a3hi = 0;
        float z3p = 0.f;
        for (int code = p; code < 125; code += 32) {
            float cf = (float)cnt3[code];
            ulonglong2 h = __ldg(&F3v[code * 8 + fl]);
            unsigned long long w2 = f2pack(cf, cf);
            a3lo = f2fma(w2, h.x, a3lo); a3hi = f2fma(w2, h.y, a3hi);
            if (fl == 0) z3p += cf * sE3[code];
        }

        // ---- phase 2c: ks2 dense over 25 codes (cnt2 derived from cnt3) ----
        unsigned long long a2lo = 0, a2hi = 0;
        float z2p = 0.f;
        if (p < 25) {
            int cnt = cnt3[p] + cnt3[p + 25] + cnt3[p + 50] + cnt3[p + 75] + cnt3[p + 100];
            if (p == c2fix) cnt++;           // position l=510 (valid for ks2 only)
            float cf = (float)cnt;
            ulonglong2 h = __ldg(&F2v[p * 8 + fl]);
            unsigned long long w2 = f2pack(cf, cf);
            a2lo = f2fma(w2, h.x, a2lo); a2hi = f2fma(w2, h.y, a2hi);
            if (fl == 0) z2p = cf * sE2[p];
        }

        // ---- reduce across the 4 groups within each warp ----
        #pragma unroll
        for (int o = 8; o <= 16; o <<= 1) {
            a0 = f2add(a0, __shfl_xor_sync(0xffffffffu, a0, o));
            a1 = f2add(a1, __shfl_xor_sync(0xffffffffu, a1, o));
            a2 = f2add(a2, __shfl_xor_sync(0xffffffffu, a2, o));
            a3 = f2add(a3, __shfl_xor_sync(0xffffffffu, a3, o));
            a2lo = f2add(a2lo, __shfl_xor_sync(0xffffffffu, a2lo, o));
            a2hi = f2add(a2hi, __shfl_xor_sync(0xffffffffu, a2hi, o));
            a3lo = f2add(a3lo, __shfl_xor_sync(0xffffffffu, a3lo, o));
            a3hi = f2add(a3hi, __shfl_xor_sync(0xffffffffu, a3hi, o));
            z2p += __shfl_xor_sync(0xffffffffu, z2p, o);
            z3p += __shfl_xor_sync(0xffffffffu, z3p, o);
        }
        if (grp == 0) {
            U2F4 u;
            u.u.x = a2lo; u.u.y = a2hi; partial[0][warp * 8 + fl] = u.f;
            u.u.x = a3lo; u.u.y = a3hi; partial[1][warp * 8 + fl] = u.f;
            int br45 = (fl < 4) ? 0 : 1;
            int g = fl & 3;
            u.u.x = a0; u.u.y = a1; partial45[br45][warp * 8 + g * 2]     = u.f;
            u.u.x = a2; u.u.y = a3; partial45[br45][warp * 8 + g * 2 + 1] = u.f;
        }
        if (lane == 0) zarr23[warp] = make_float2(z2p, z3p);
        __syncthreads();

        // ---- combine warps + normalize by Z ----
        if (tid < 32) {
            int br = tid >> 3, f = tid & 7;
            float4 s = {0,0,0,0};
            #pragma unroll
            for (int w8 = 0; w8 < 8; w8++) {
                float4 pq = (br < 2) ? partial[br][w8 * 8 + f]
                                     : partial45[br - 2][w8 * 8 + f];
                s.x += pq.x; s.y += pq.y; s.z += pq.z; s.w += pq.w;
            }
            float Z = 0.f;
            #pragma unroll
            for (int w8 = 0; w8 < 8; w8++) {
                Z += (br == 0) ? zarr23[w8].x : (br == 1) ? zarr23[w8].y
                   : (br == 2) ? zarr45[w8].x : zarr45[w8].y;
            }
            float iz = 1.0f / Z;
            s.x *= iz; s.y *= iz; s.z *= iz; s.w *= iz;
            feats4[br * 8 + f] = s;
        }
        __syncthreads();

        // ---- proj (128->64) across all 256 threads, transposed weights ----
        {
            const float* sfeat = (const float*)feats4;
            int o = tid & 63, q = tid >> 6;
            const float* wt = g_Wt + (q * 32) * 64 + o;
            const float* fk = sfeat + q * 32;
            float acc = 0.f;
            #pragma unroll
            for (int kk = 0; kk < 32; kk++)
                acc = fmaf(fk[kk], __ldg(&wt[kk * 64]), acc);
            prsum[tid] = acc;
        }
        __syncthreads();

        // ---- gelu + layernorm ----
        float z = 0.f;
        if (tid < 64) {
            z = __ldg(&proj_b[tid]) + prsum[tid] + prsum[64 + tid] + prsum[128 + tid] + prsum[192 + tid];
            z = gelu_exact(z);
            lnred[tid] = z;
            lnred[64 + tid] = z * z;
        }
        __syncthreads();
        if (tid < 32) {
            float s = lnred[tid] + lnred[tid + 32];
            float q = lnred[64 + tid] + lnred[96 + tid];
            #pragma unroll
            for (int o = 16; o; o >>= 1) {
                s += __shfl_xor_sync(0xffffffffu, s, o);
                q += __shfl_xor_sync(0xffffffffu, q, o);
            }
            if (tid == 0) {
                float mu  = s * (1.0f / 64.0f);
                float var = q * (1.0f / 64.0f) - mu * mu;
                lnstats[0] = mu;
                lnstats[1] = rsqrtf(var + 1e-5f);
            }
        }
        __syncthreads();
        if (tid < 64)
            out[row * 64 + tid] = (z - lnstats[0]) * lnstats[1] * __ldg(&gamma[tid]) + __ldg(&beta[tid]);
        __syncthreads();
    }
}

// ---------------------------------------------------------------------------
extern "C" void kernel_launch(void* const* d_in, const int* in_sizes, int n_in,
                              void* d_out, int out_size)
{
    (void)in_sizes; (void)n_in; (void)out_size;
    const int*   x_idx  = (const int*)  d_in[0];
    const float* emb    = (const float*)d_in[1];
    const float* cw[4], *cb[4], *aw[4];
    for (int i = 0; i < 4; i++) {
        cw[i] = (const float*)d_in[2 + 4 * i];
        cb[i] = (const float*)d_in[3 + 4 * i];
        aw[i] = (const float*)d_in[4 + 4 * i];
    }
    const float* proj_w = (const float*)d_in[18];
    const float* proj_b = (const float*)d_in[19];
    const float* gamma  = (const float*)d_in[20];
    const float* beta   = (const float*)d_in[21];

    setup_kernel<<<NB_CODE + 5, 256>>>(emb,
        cw[0], cb[0], aw[0],
        cw[1], cb[1], aw[1],
        cw[2], cb[2], aw[2],
        cw[3], cb[3], aw[3],
        proj_w);

    seqcnn_main<<<GRID_MAIN, 256>>>(x_idx, proj_b, gamma, beta, (float*)d_out);
}

// round 17
// speedup vs baseline: 1.2320x; 1.2320x over previous
#include <cuda_runtime.h>
#include <cuda_fp16.h>
#include <math.h>

#define BATCH 4096
#define SEQL 512
#define GRID_MAIN 888
#define NB_CODE 98             // 32 codes per block, one per warp (1024 threads)

__device__ __align__(128) float    g_F2[25 * 32];     // e2*h2 (fp32)
__device__ __align__(128) float    g_F3[125 * 32];    // e3*h3 (fp32)
// fused record by c5: [32 x fp16 (e4*h4 of c5%625) | 32 x fp16 (e5*h5)]
// record 3125 = zeros; records 3126+c4 = [F4(c4) | zeros] for the l=508 edge
__device__ __align__(128) unsigned g_F45h[3751 * 32];
__device__ __align__(128) float2   g_E45[3125];       // (e4[c%625], e5[c]) fp32
__device__ __align__(128) float    g_E3[125], g_E2[25];
__device__ __align__(128) float    g_Wt[128 * 64];    // proj_w transposed
__device__ unsigned g_row_ctr;

__device__ __forceinline__ float gelu_exact(float x) {
    return 0.5f * x * (1.0f + erff(x * 0.70710678118654752440f));
}
__device__ __forceinline__ unsigned long long f2add(unsigned long long a, unsigned long long b) {
    unsigned long long r; asm("add.rn.f32x2 %0,%1,%2;" : "=l"(r) : "l"(a), "l"(b)); return r;
}
__device__ __forceinline__ unsigned long long f2fma(unsigned long long a, unsigned long long b, unsigned long long c) {
    unsigned long long r; asm("fma.rn.f32x2 %0,%1,%2,%3;" : "=l"(r) : "l"(a), "l"(b), "l"(c)); return r;
}
__device__ __forceinline__ unsigned long long f2pack(float lo, float hi) {
    unsigned long long r; asm("mov.b64 %0,{%1,%2};" : "=l"(r) : "f"(lo), "f"(hi)); return r;
}
__device__ __forceinline__ unsigned long long h2f2(unsigned u) {
    __half2 h = *(__half2*)&u;
    float2 f = __half22float2(h);
    return f2pack(f.x, f.y);
}
union U2F4 { ulonglong2 u; float4 f; };

// ---------------------------------------------------------------------------
// Fused setup kernel — 1024 threads, ONE code per warp (no staging redundancy).
// Blocks 0..97 : 32 codes each. Blocks 98..101: Wt transpose. Block 102: init.
// ---------------------------------------------------------------------------
__global__ __launch_bounds__(1024) void setup_kernel(
    const float* __restrict__ emb,
    const float* __restrict__ w0, const float* __restrict__ b0, const float* __restrict__ a0,
    const float* __restrict__ w1, const float* __restrict__ b1, const float* __restrict__ a1,
    const float* __restrict__ w2, const float* __restrict__ b2, const float* __restrict__ a2,
    const float* __restrict__ w3, const float* __restrict__ b3, const float* __restrict__ a3,
    const float* __restrict__ proj_w)
{
    const int b = blockIdx.x, tid = threadIdx.x, lane = tid & 31, warp = tid >> 5;

    if (b >= NB_CODE) {
        if (b < NB_CODE + 4) {
            // 2048 elements per block, 1024 threads -> 2 elements each
            #pragma unroll
            for (int r = 0; r < 2; r++) {
                int j = (b - NB_CODE) * 2048 + r * 1024 + tid;
                int k = j >> 6, o = j & 63;
                g_Wt[j] = __ldg(&proj_w[o * 128 + k]);
            }
        } else {
            if (tid == 0) g_row_ctr = 0;
            if (tid < 32) g_F45h[3125 * 32 + tid] = 0u;
        }
        return;
    }

    __shared__ float pdall[14 * 160];
    __shared__ float sb[4][32], sa[4][32];
    for (int i = tid; i < 14 * 160; i += 1024) {
        int l8 = i & 31;
        int t  = (i >> 5) % 5;
        int slot = i / 160;
        const float* W; int KS, j;
        if (slot < 2)      { W = w0; KS = 2; j = slot; }
        else if (slot < 5) { W = w1; KS = 3; j = slot - 2; }
        else if (slot < 9) { W = w2; KS = 4; j = slot - 5; }
        else               { W = w3; KS = 5; j = slot - 9; }
        float acc = 0.f;
        #pragma unroll
        for (int c = 0; c < 8; c++)
            acc += __ldg(&emb[t * 8 + c]) * __ldg(&W[l8 * 8 * KS + c * KS + j]);
        pdall[slot * 160 + t * 32 + l8] = acc;
    }
    if (tid < 128) {
        int br = tid >> 5, f = tid & 31;
        const float* Bv = (br == 0) ? b0 : (br == 1) ? b1 : (br == 2) ? b2 : b3;
        const float* Av = (br == 0) ? a0 : (br == 1) ? a1 : (br == 2) ? a2 : a3;
        sb[br][f] = __ldg(&Bv[f]);
        sa[br][f] = __ldg(&Av[f]);
    }
    __syncthreads();

    const int c = b * 32 + warp;      // one code per warp
    if (c >= 3125) return;
    {
        int t0 = c % 5, r = c / 5;
        int t1 = r % 5; r /= 5;
        int t2 = r % 5; r /= 5;
        int t3 = r % 5, t4 = r / 5;

        float acc2 = sb[0][lane] + pdall[0*160 + t0*32 + lane] + pdall[1*160 + t1*32 + lane];
        float acc3 = sb[1][lane] + pdall[2*160 + t0*32 + lane] + pdall[3*160 + t1*32 + lane]
                                 + pdall[4*160 + t2*32 + lane];
        float acc4 = sb[2][lane] + pdall[5*160 + t0*32 + lane] + pdall[6*160 + t1*32 + lane]
                                 + pdall[7*160 + t2*32 + lane] + pdall[8*160 + t3*32 + lane];
        float acc5 = sb[3][lane] + pdall[9*160 + t0*32 + lane] + pdall[10*160 + t1*32 + lane]
                                 + pdall[11*160 + t2*32 + lane] + pdall[12*160 + t3*32 + lane]
                                 + pdall[13*160 + t4*32 + lane];
        float h2 = gelu_exact(acc2), h3 = gelu_exact(acc3);
        float h4 = gelu_exact(acc4), h5 = gelu_exact(acc5);

        float s2 = h2 * sa[0][lane], s3 = h3 * sa[1][lane];
        float s4 = h4 * sa[2][lane], s5 = h5 * sa[3][lane];
        #pragma unroll
        for (int o = 16; o; o >>= 1) {
            s2 += __shfl_xor_sync(0xffffffffu, s2, o);
            s3 += __shfl_xor_sync(0xffffffffu, s3, o);
            s4 += __shfl_xor_sync(0xffffffffu, s4, o);
            s5 += __shfl_xor_sync(0xffffffffu, s5, o);
        }
        float e2 = __expf(s2), e3 = __expf(s3), e4 = __expf(s4), e5 = __expf(s5);

        // ---- fused ks4/ks5 record (e4 == E4[c%625] since acc4 uses t0..t3) ----
        {
            float v4 = h4 * e4, v5 = h5 * e5;
            int src = (lane & 15) * 2;
            float lo4 = __shfl_sync(0xffffffffu, v4, src);
            float hi4 = __shfl_sync(0xffffffffu, v4, src + 1);
            float lo5 = __shfl_sync(0xffffffffu, v5, src);
            float hi5 = __shfl_sync(0xffffffffu, v5, src + 1);
            __half2 p4 = __floats2half2_rn(lo4, hi4);
            __half2 p5 = __floats2half2_rn(lo5, hi5);
            unsigned u4 = *(unsigned*)&p4, u5 = *(unsigned*)&p5;
            unsigned u = (lane < 16) ? u4 : u5;
            g_F45h[c * 32 + lane] = u;
            if (c < 625)   // edge record for l=508: F4 valid, F5 zero
                g_F45h[(3126 + c) * 32 + lane] = (lane < 16) ? u4 : 0u;
        }
        if (lane == 0) g_E45[c] = make_float2(e4, e5);
        if (c < 125) { g_F3[c * 32 + lane] = h3 * e3; if (lane == 0) g_E3[c] = e3; }
        if (c < 25)  { g_F2[c * 32 + lane] = h2 * e2; if (lane == 0) g_E2[c] = e2; }
    }
}

// ---------------------------------------------------------------------------
// Persistent main kernel: fused pooling; E45 gather deferred past pooling.
// ---------------------------------------------------------------------------
__global__ __launch_bounds__(256, 6) void seqcnn_main(
    const int*   __restrict__ x_idx,
    const float* __restrict__ proj_b,
    const float* __restrict__ gamma,
    const float* __restrict__ beta,
    float*       __restrict__ out)
{
    __shared__ unsigned char  xrow[SEQL + 8];
    __shared__ unsigned short code5[SEQL];    // fused record index (0..3750)
    __shared__ int            cnt3[125];
    __shared__ int            c2fix;
    __shared__ float          sE3[125];
    __shared__ float          sE2[25];
    __shared__ float2         zarr45[8];
    __shared__ float2         zarr23[8];
    __shared__ float4         partial[2][64];   // ks2, ks3
    __shared__ float4         partial45[2][64]; // ks4, ks5 (from fused lanes)
    __shared__ float4         feats4[32];       // viewed as float[128]
    __shared__ float          prsum[256];
    __shared__ float          lnred[128];
    __shared__ float          lnstats[2];
    __shared__ unsigned       row_sh;

    const int tid = threadIdx.x, lane = tid & 31, warp = tid >> 5;
    const int grp = lane >> 3, fl = lane & 7;
    const ulonglong2* F2v = (const ulonglong2*)g_F2;
    const ulonglong2* F3v = (const ulonglong2*)g_F3;
    const uint4*      F45 = (const uint4*)g_F45h;   // record = 8 x uint4

    if (tid < 125) sE3[tid] = g_E3[tid];
    if (tid >= 128 && tid < 153) sE2[tid - 128] = g_E2[tid - 128];

    for (;;) {
        if (tid == 0) row_sh = atomicAdd(&g_row_ctr, 1u);
        __syncthreads();
        const unsigned row = row_sh;
        if (row >= BATCH) break;

        // ---- phase 0: stage row (vectorized) + zero counts ----
        {
            const int4* src = (const int4*)(x_idx + row * SEQL);
            if (tid < 128) {
                int4 v = __ldg(&src[tid]);
                uchar4 pk = make_uchar4((unsigned char)v.x, (unsigned char)v.y,
                                        (unsigned char)v.z, (unsigned char)v.w);
                *(uchar4*)&xrow[tid * 4] = pk;
            }
        }
        if (tid < 8) xrow[SEQL + tid] = 0;
        if (tid < 125) cnt3[tid] = 0;
        __syncthreads();

        // ---- phase 1: integer hist + codes (no gmem at all) ----
        {
            const int la = tid, lb = tid + 256;
            int x0a = xrow[la], x1a = xrow[la+1], x2a = xrow[la+2], x3a = xrow[la+3], x4a = xrow[la+4];
            int x0b = xrow[lb], x1b = xrow[lb+1], x2b = xrow[lb+2], x3b = xrow[lb+3], x4b = xrow[lb+4];
            int c3a = x0a + 5*x1a + 25*x2a, c4a = c3a + 125*x3a, c5a = c4a + 625*x4a;
            int c2b = x0b + 5*x1b;
            int c3b = c2b + 25*x2b, c4b = c3b + 125*x3b, c5b = c4b + 625*x4b;

            atomicAdd(&cnt3[c3a], 1);
            code5[la] = (unsigned short)c5a;

            if (lb < 510) atomicAdd(&cnt3[c3b], 1);
            int c5s = (lb < 508) ? c5b : (lb == 508 ? 3126 + c4b : 3125);
            code5[lb] = (unsigned short)c5s;
            if (lb == 510) c2fix = c2b;
        }
        __syncthreads();

        const int p = warp * 4 + grp;   // group id 0..31

        // ---- phase 2a: fused ks4+ks5 pooling: ONE LDG.128 per position ----
        unsigned long long a0 = 0, a1 = 0, a2 = 0, a3 = 0;
        #pragma unroll 4
        for (int it = 0; it < 16; it++) {
            int c5 = code5[p + it * 32];
            uint4 q = __ldg(&F45[c5 * 8 + fl]);
            a0 = f2add(a0, h2f2(q.x));
            a1 = f2add(a1, h2f2(q.y));
            a2 = f2add(a2, h2f2(q.z));
            a3 = f2add(a3, h2f2(q.w));
        }

        // ---- deferred Z4/Z5 gather: overlaps with dense phases below ----
        float z4, z5;
        {
            int s0 = code5[tid];            // always a real code (<3125)
            int s1 = code5[tid + 256];      // c5 | 3126+c4 (l=508) | 3125 (invalid)
            float2 e0 = __ldg(&g_E45[s0]);
            int idx = (s1 < 3125) ? s1 : (s1 > 3125 ? s1 - 3126 : 0);
            float2 e1 = __ldg(&g_E45[idx]); // E45[c4].x == e4[c4] (t4=0 code)
            z4 = e0.x; z5 = e0.y;
            if (s1 != 3125) z4 += e1.x;
            if (s1 <  3125) z5 += e1.y;
        }

        // ---- phase 2b: ks3 dense over 125 codes (counts as weights) ----
        unsigned long long a3lo = 0, a3hi = 0;
        float z3p = 0.f;
        for (int code = p; code < 125; code += 32) {
            float cf = (float)cnt3[code];
            ulonglong2 h = __ldg(&F3v[code * 8 + fl]);
            unsigned long long w2 = f2pack(cf, cf);
            a3lo = f2fma(w2, h.x, a3lo); a3hi = f2fma(w2, h.y, a3hi);
            if (fl == 0) z3p += cf * sE3[code];
        }

        // ---- phase 2c: ks2 dense over 25 codes (cnt2 derived from cnt3) ----
        unsigned long long a2lo = 0, a2hi = 0;
        float z2p = 0.f;
        if (p < 25) {
            int cnt = cnt3[p] + cnt3[p + 25] + cnt3[p + 50] + cnt3[p + 75] + cnt3[p + 100];
            if (p == c2fix) cnt++;           // position l=510 (valid for ks2 only)
            float cf = (float)cnt;
            ulonglong2 h = __ldg(&F2v[p * 8 + fl]);
            unsigned long long w2 = f2pack(cf, cf);
            a2lo = f2fma(w2, h.x, a2lo); a2hi = f2fma(w2, h.y, a2hi);
            if (fl == 0) z2p = cf * sE2[p];
        }

        // ---- reduce: groups (o=8,16) for pooled sums; full warp for Z4/Z5 ----
        #pragma unroll
        for (int o = 8; o <= 16; o <<= 1) {
            a0 = f2add(a0, __shfl_xor_sync(0xffffffffu, a0, o));
            a1 = f2add(a1, __shfl_xor_sync(0xffffffffu, a1, o));
            a2 = f2add(a2, __shfl_xor_sync(0xffffffffu, a2, o));
            a3 = f2add(a3, __shfl_xor_sync(0xffffffffu, a3, o));
            a2lo = f2add(a2lo, __shfl_xor_sync(0xffffffffu, a2lo, o));
            a2hi = f2add(a2hi, __shfl_xor_sync(0xffffffffu, a2hi, o));
            a3lo = f2add(a3lo, __shfl_xor_sync(0xffffffffu, a3lo, o));
            a3hi = f2add(a3hi, __shfl_xor_sync(0xffffffffu, a3hi, o));
            z2p += __shfl_xor_sync(0xffffffffu, z2p, o);
            z3p += __shfl_xor_sync(0xffffffffu, z3p, o);
        }
        #pragma unroll
        for (int o = 16; o; o >>= 1) {
            z4 += __shfl_xor_sync(0xffffffffu, z4, o);
            z5 += __shfl_xor_sync(0xffffffffu, z5, o);
        }
        if (grp == 0) {
            U2F4 u;
            u.u.x = a2lo; u.u.y = a2hi; partial[0][warp * 8 + fl] = u.f;
            u.u.x = a3lo; u.u.y = a3hi; partial[1][warp * 8 + fl] = u.f;
            int br45 = (fl < 4) ? 0 : 1;
            int g = fl & 3;
            u.u.x = a0; u.u.y = a1; partial45[br45][warp * 8 + g * 2]     = u.f;
            u.u.x = a2; u.u.y = a3; partial45[br45][warp * 8 + g * 2 + 1] = u.f;
        }
        if (lane == 0) {
            zarr23[warp] = make_float2(z2p, z3p);
            zarr45[warp] = make_float2(z4, z5);
        }
        __syncthreads();

        // ---- combine warps + normalize by Z ----
        if (tid < 32) {
            int br = tid >> 3, f = tid & 7;
            float4 s = {0,0,0,0};
            #pragma unroll
            for (int w8 = 0; w8 < 8; w8++) {
                float4 pq = (br < 2) ? partial[br][w8 * 8 + f]
                                     : partial45[br - 2][w8 * 8 + f];
                s.x += pq.x; s.y += pq.y; s.z += pq.z; s.w += pq.w;
            }
            float Z = 0.f;
            #pragma unroll
            for (int w8 = 0; w8 < 8; w8++) {
                Z += (br == 0) ? zarr23[w8].x : (br == 1) ? zarr23[w8].y
                   : (br == 2) ? zarr45[w8].x : zarr45[w8].y;
            }
            float iz = 1.0f / Z;
            s.x *= iz; s.y *= iz; s.z *= iz; s.w *= iz;
            feats4[br * 8 + f] = s;
        }
        __syncthreads();

        // ---- proj (128->64) across all 256 threads, transposed weights ----
        {
            const float* sfeat = (const float*)feats4;
            int o = tid & 63, q = tid >> 6;
            const float* wt = g_Wt + (q * 32) * 64 + o;
            const float* fk = sfeat + q * 32;
            float acc = 0.f;
            #pragma unroll
            for (int kk = 0; kk < 32; kk++)
                acc = fmaf(fk[kk], __ldg(&wt[kk * 64]), acc);
            prsum[tid] = acc;
        }
        __syncthreads();

        // ---- gelu + layernorm ----
        float z = 0.f;
        if (tid < 64) {
            z = __ldg(&proj_b[tid]) + prsum[tid] + prsum[64 + tid] + prsum[128 + tid] + prsum[192 + tid];
            z = gelu_exact(z);
            lnred[tid] = z;
            lnred[64 + tid] = z * z;
        }
        __syncthreads();
        if (tid < 32) {
            float s = lnred[tid] + lnred[tid + 32];
            float q = lnred[64 + tid] + lnred[96 + tid];
            #pragma unroll
            for (int o = 16; o; o >>= 1) {
                s += __shfl_xor_sync(0xffffffffu, s, o);
                q += __shfl_xor_sync(0xffffffffu, q, o);
            }
            if (tid == 0) {
                float mu  = s * (1.0f / 64.0f);
                float var = q * (1.0f / 64.0f) - mu * mu;
                lnstats[0] = mu;
                lnstats[1] = rsqrtf(var + 1e-5f);
            }
        }
        __syncthreads();
        if (tid < 64)
            out[row * 64 + tid] = (z - lnstats[0]) * lnstats[1] * __ldg(&gamma[tid]) + __ldg(&beta[tid]);
        __syncthreads();
    }
}

// ---------------------------------------------------------------------------
extern "C" void kernel_launch(void* const* d_in, const int* in_sizes, int n_in,
                              void* d_out, int out_size)
{
    (void)in_sizes; (void)n_in; (void)out_size;
    const int*   x_idx  = (const int*)  d_in[0];
    const float* emb    = (const float*)d_in[1];
    const float* cw[4], *cb[4], *aw[4];
    for (int i = 0; i < 4; i++) {
        cw[i] = (const float*)d_in[2 + 4 * i];
        cb[i] = (const float*)d_in[3 + 4 * i];
        aw[i] = (const float*)d_in[4 + 4 * i];
    }
    const float* proj_w = (const float*)d_in[18];
    const float* proj_b = (const float*)d_in[19];
    const float* gamma  = (const float*)d_in[20];
    const float* beta   = (const float*)d_in[21];

    setup_kernel<<<NB_CODE + 5, 1024>>>(emb,
        cw[0], cb[0], aw[0],
        cw[1], cb[1], aw[1],
        cw[2], cb[2], aw[2],
        cw[3], cb[3], aw[3],
        proj_w);

    seqcnn_main<<<GRID_MAIN, 256>>>(x_idx, proj_b, gamma, beta, (float*)d_out);
}